// round 11
// baseline (speedup 1.0000x reference)
#include <cuda_runtime.h>
#include <math.h>

#define TT 1024
#define BB 32
#define DD 256
#define HH 512
#define G4 2048   // 4*H
#define OO 256
#define MM (TT * BB)
#define NCTA 128
#define NGRP 4
#define GSZ  32     // CTAs per group
#define GB   8      // batch per group

typedef unsigned long long u64;

// ---- packed fp32x2 helpers (sm_103a FFMA2, exact fp32 numerics) ----
__device__ __forceinline__ u64 ffma2(u64 a, u64 b, u64 c) {
    u64 d; asm("fma.rn.f32x2 %0, %1, %2, %3;" : "=l"(d) : "l"(a), "l"(b), "l"(c)); return d;
}
__device__ __forceinline__ u64 dup2(float x) {
    u64 d; unsigned xi = __float_as_uint(x);
    asm("mov.b64 %0, {%1, %1};" : "=l"(d) : "r"(xi)); return d;
}
__device__ __forceinline__ float2 unpk(u64 a) {
    unsigned lo, hi; asm("mov.b64 {%0, %1}, %2;" : "=r"(lo), "=r"(hi) : "l"(a));
    return make_float2(__uint_as_float(lo), __uint_as_float(hi));
}
__device__ __forceinline__ float fsig(float y) { return __fdividef(1.f, 1.f + __expf(-y)); }
__device__ __forceinline__ float ftanh(float x) { return 2.f * fsig(2.f * x) - 1.f; }

// ---- gpu-scope acquire/release flag ops (no MEMBAR.ALL.GPU in the tail) ----
__device__ __forceinline__ unsigned ld_acq(const unsigned int* p) {
    unsigned v; asm volatile("ld.acquire.gpu.global.u32 %0, [%1];" : "=r"(v) : "l"(p) : "memory");
    return v;
}
__device__ __forceinline__ void st_rel(unsigned int* p, unsigned v) {
    asm volatile("st.release.gpu.global.u32 [%0], %1;" :: "l"(p), "r"(v) : "memory");
}

// Scratch (device globals: allocation-free rule)
__device__ float g_xp[(size_t)TT * G4 * BB];          // [T][4H][B] pre-activations (+ biases)
__device__ float g_h[(size_t)NGRP * TT * HH * GB];    // [g][t][k][8] group-local k-major data
__device__ float g_wt[(size_t)HH * G4];               // [K][4H] k-major weights (per layer)
__device__ unsigned int g_flag[NCTA * 32];            // per-CTA epoch flags, 128B apart

// ---------------------------------------------------------------------------
// Transpose x[B][T][D] -> g_h[(g*T + t)*D + d][8] ; block(0,0) zeroes flags.
// ---------------------------------------------------------------------------
__global__ void transpose_x_kernel(const float* __restrict__ x, float* __restrict__ gh)
{
    const int t  = blockIdx.x;
    const int d0 = blockIdx.y * 32;
    const int tid = threadIdx.x;
    if (blockIdx.x == 0 && blockIdx.y == 0 && tid < NCTA) g_flag[tid * 32] = 0u;
    __shared__ float s[32][36];
    {
        int b  = tid >> 3;
        int d4 = (tid & 7) * 4;
        float4 v = *(const float4*)(x + (size_t)b * TT * DD + (size_t)t * DD + d0 + d4);
        s[b][d4 + 0] = v.x; s[b][d4 + 1] = v.y; s[b][d4 + 2] = v.z; s[b][d4 + 3] = v.w;
    }
    __syncthreads();
    {
        int d  = tid >> 3;
        int b4 = (tid & 7) * 4;
        int g  = b4 >> 3;
        int off= b4 & 7;
        float4 o = make_float4(s[b4 + 0][d], s[b4 + 1][d], s[b4 + 2][d], s[b4 + 3][d]);
        *(float4*)(gh + (((size_t)g * TT + t) * DD + d0 + d) * GB + off) = o;
    }
}

// ---------------------------------------------------------------------------
// Transpose W[2048][K] -> wt[K][2048].
// ---------------------------------------------------------------------------
__global__ void transpose_w_kernel(const float* __restrict__ W, float* __restrict__ wt, int K)
{
    const int n0 = blockIdx.x * 32;
    const int k0 = blockIdx.y * 32;
    const int tid = threadIdx.x;
    __shared__ float s[32][36];
    {
        int n  = tid >> 3;
        int k4 = (tid & 7) * 4;
        float4 v = *(const float4*)(W + (size_t)(n0 + n) * K + k0 + k4);
        s[n][k4 + 0] = v.x; s[n][k4 + 1] = v.y; s[n][k4 + 2] = v.z; s[n][k4 + 3] = v.w;
    }
    __syncthreads();
    {
        int k  = tid >> 3;
        int n4 = (tid & 7) * 4;
        float4 o = make_float4(s[n4 + 0][k], s[n4 + 1][k], s[n4 + 2][k], s[n4 + 3][k]);
        *(float4*)(wt + (size_t)(k0 + k) * G4 + n0 + n4) = o;
    }
}

// ---------------------------------------------------------------------------
// Projection GEMM: xp[t][n][b] = sum_k wt[k][n] * gh[(g*T+t)*K + k][b&7] + bias
// ---------------------------------------------------------------------------
__global__ void __launch_bounds__(256, 2)
proj_kernel(const float* __restrict__ wt,
            const float* __restrict__ bx,
            const float* __restrict__ bh,
            const float* __restrict__ gh,
            int K,
            float* __restrict__ xp)
{
    const int n0  = blockIdx.x * 256;
    const int m0  = blockIdx.y * 64;
    const int tid = threadIdx.x;
    const int ng  = tid >> 3;
    const int mg  = tid & 7;

    __shared__ float Ws[16][264];
    __shared__ float Xs[16][72];

    u64 acc[4][8];
#pragma unroll
    for (int i = 0; i < 4; i++)
#pragma unroll
        for (int j = 0; j < 8; j++) acc[i][j] = 0ULL;

    const int xk  = tid >> 4;
    const int xm4 = (tid & 15) * 4;
    const int xt  = (m0 >> 5) + (xm4 >> 5);
    const int xb4 = xm4 & 31;
    const int xg  = xb4 >> 3;
    const int xoff= xb4 & 7;
    const float* xsrc = gh + (((size_t)xg * TT + xt) * K) * GB + xoff;

    for (int k0 = 0; k0 < K; k0 += 16) {
        __syncthreads();
#pragma unroll
        for (int i = 0; i < 4; i++) {
            int id = i * 256 + tid;
            int k  = id >> 6;
            int n4 = (id & 63) * 4;
            float4 v = *(const float4*)(wt + (size_t)(k0 + k) * G4 + n0 + n4);
            *(float4*)&Ws[k][n4] = v;
        }
        {
            float4 v = *(const float4*)(xsrc + (size_t)(k0 + xk) * GB);
            *(float4*)&Xs[xk][xm4] = v;
        }
        __syncthreads();

#pragma unroll
        for (int k = 0; k < 16; k++) {
            const ulonglong2* wp = (const ulonglong2*)&Ws[k][ng * 8];
            ulonglong2 wA = wp[0];
            ulonglong2 wB = wp[1];
            float4 x0 = *(const float4*)&Xs[k][mg * 8];
            float4 x1 = *(const float4*)&Xs[k][mg * 8 + 4];
            u64 xd[8] = {dup2(x0.x), dup2(x0.y), dup2(x0.z), dup2(x0.w),
                         dup2(x1.x), dup2(x1.y), dup2(x1.z), dup2(x1.w)};
            u64 wv[4] = {wA.x, wA.y, wB.x, wB.y};
#pragma unroll
            for (int i = 0; i < 4; i++)
#pragma unroll
                for (int j = 0; j < 8; j++)
                    acc[i][j] = ffma2(wv[i], xd[j], acc[i][j]);
        }
    }

    float bias[8];
#pragma unroll
    for (int r = 0; r < 8; r++) {
        int n = n0 + ng * 8 + r;
        bias[r] = bx[n] + bh[n];
    }
    const int ot = (m0 >> 5) + (mg >> 2);
    const int ob = (mg & 3) * 8;
    float* outb = xp + ((size_t)ot * G4 + n0 + ng * 8) * BB + ob;
#pragma unroll
    for (int i = 0; i < 4; i++) {
        float2 p[8];
#pragma unroll
        for (int j = 0; j < 8; j++) p[j] = unpk(acc[i][j]);
        int rlo = 2 * i, rhi = 2 * i + 1;
        *(float4*)(outb + (size_t)rlo * BB)     = make_float4(p[0].x + bias[rlo], p[1].x + bias[rlo], p[2].x + bias[rlo], p[3].x + bias[rlo]);
        *(float4*)(outb + (size_t)rlo * BB + 4) = make_float4(p[4].x + bias[rlo], p[5].x + bias[rlo], p[6].x + bias[rlo], p[7].x + bias[rlo]);
        *(float4*)(outb + (size_t)rhi * BB)     = make_float4(p[0].y + bias[rhi], p[1].y + bias[rhi], p[2].y + bias[rhi], p[3].y + bias[rhi]);
        *(float4*)(outb + (size_t)rhi * BB + 4) = make_float4(p[4].y + bias[rhi], p[5].y + bias[rhi], p[6].y + bias[rhi], p[7].y + bias[rhi]);
    }
}

// ---------------------------------------------------------------------------
// Persistent LSTM — R6 winner structure with two additive deltas:
//   * HSH2: h staged PRE-DUPLICATED as (h,h) u64 pairs -> GEMM inner loop has
//     zero MOVs (3 LDS.128 + 8 FFMA2 per k).
//   * xp prefetch depth 2 (covers DRAM latency fully).
// SMEM: WSH 128KB + HSH2 32KB + RED 16KB + GT 2KB = 178KB.
// ---------------------------------------------------------------------------
#define LSTM_SMEM_FLOATS (512*64 + 512*8*2 + 8*64*8 + 64*8)
#define LSTM_SMEM_BYTES  (LSTM_SMEM_FLOATS * 4)

__global__ void __launch_bounds__(256, 1)
lstm_kernel(const float* __restrict__ Wh,   // [4][H][H]
            const float* __restrict__ xp,   // [T][4H][B]
            float* __restrict__ gh,         // [g][T][512][8]
            unsigned int ebase)             // flag epoch base (layer*TT)
{
    extern __shared__ float sm[];
    float* WSH  = sm;                     // [k][64 rows]             128KB
    u64*   HSH2 = (u64*)(sm + 512 * 64);  // [k*8+b] = (h,h)          32KB
    float* RED  = sm + 512 * 64 + 512 * 8 * 2;  // [w][64 rows][8]    16KB
    float* GT   = RED + 8 * 64 * 8;       // [64 rows][8]             2KB

    const int tid   = threadIdx.x;
    const int rank  = blockIdx.x & 31;
    const int group = blockIdx.x >> 5;
    const int j0    = rank * 16;
    const int gb0   = group * GB;
    const int w     = tid >> 5;
    const int lane  = tid & 31;
    const int rgr   = lane >> 1;
    const int bgr   = lane & 1;

    unsigned int* flags = g_flag;

    // Preload Wh slice transposed: rows r = gate*16 + jl
    for (int f = tid; f < 64 * 128; f += 256) {
        int r  = f >> 7;
        int c4 = (f & 127) * 4;
        int gate = r >> 4, jl = r & 15;
        float4 v = *(const float4*)(Wh + ((size_t)gate * HH + j0 + jl) * HH + c4);
        WSH[(c4 + 0) * 64 + r] = v.x; WSH[(c4 + 1) * 64 + r] = v.y;
        WSH[(c4 + 2) * 64 + r] = v.z; WSH[(c4 + 3) * 64 + r] = v.w;
    }
    for (int i = tid; i < 512 * 8; i += 256) HSH2[i] = 0ULL;   // h_{-1}=0
    __syncthreads();

    // Per-thread fixed indices
    const int gr   = tid >> 1;          // GT staging row (tid<128)
    const int ghalf= tid & 1;
    const int ggate= gr >> 4, gjl = gr & 15;
    const float* xpsrc = xp + ((size_t)ggate * HH + j0 + gjl) * BB + gb0 + ghalf * 4;
    const int sjl  = tid >> 3;          // state j (tid<128)
    const int sbb  = tid & 7;

    float* ghg = gh + (size_t)group * TT * HH * GB;
    float creg = 0.f;                   // cell state in register (tid<128)

    // Prologue: depth-2 xp prefetch
    float4 xpv0, xpv1;
    if (tid < 128) {
        xpv0 = __ldcg((const float4*)xpsrc);
        xpv1 = __ldcg((const float4*)(xpsrc + (size_t)G4 * BB));
    }

    for (int t = 0; t < TT; t++) {
        // 1) load h_{t-1} (16KB linear), stage duplicated into HSH2; stage GT
        if (t > 0) {
            const float* hb = ghg + (size_t)(t - 1) * HH * GB;
            float4 hv[4];
#pragma unroll
            for (int i = 0; i < 4; i++)
                hv[i] = __ldcg((const float4*)(hb + (size_t)(i * 256 + tid) * 4));
#pragma unroll
            for (int i = 0; i < 4; i++) {
                int base = (i * 256 + tid) * 4;     // u64 index = k*8+b
                ulonglong2 p0, p1;
                p0.x = dup2(hv[i].x); p0.y = dup2(hv[i].y);
                p1.x = dup2(hv[i].z); p1.y = dup2(hv[i].w);
                *(ulonglong2*)(HSH2 + base)     = p0;
                *(ulonglong2*)(HSH2 + base + 2) = p1;
            }
        }
        if (tid < 128) *(float4*)&GT[gr * GB + ghalf * 4] = xpv0;
        __syncthreads();                                   // (1)

        // 2) FFMA2 partial GEMM: 4 rows x 4 b per thread over a 64-wide k slice
        //    inner loop: 3 LDS.128 + 8 FFMA2, zero MOVs
        u64 acc2[2][4];
#pragma unroll
        for (int p = 0; p < 2; p++)
#pragma unroll
            for (int j = 0; j < 4; j++) acc2[p][j] = 0ULL;

        const int kbase = w * 64;
        const int r0 = rgr * 4;
        const int b0 = bgr * 4;
#pragma unroll 8
        for (int kk = 0; kk < 64; kk++) {
            int k = kbase + kk;
            ulonglong2 wv = *(const ulonglong2*)&WSH[k * 64 + r0];
            const u64* hp = HSH2 + (k * 8 + b0);
            ulonglong2 hA = *(const ulonglong2*)hp;        // (h_b0,h_b0),(h_b1,h_b1)
            ulonglong2 hB = *(const ulonglong2*)(hp + 2);  // (h_b2,..),(h_b3,..)
            acc2[0][0] = ffma2(wv.x, hA.x, acc2[0][0]);
            acc2[0][1] = ffma2(wv.x, hA.y, acc2[0][1]);
            acc2[0][2] = ffma2(wv.x, hB.x, acc2[0][2]);
            acc2[0][3] = ffma2(wv.x, hB.y, acc2[0][3]);
            acc2[1][0] = ffma2(wv.y, hA.x, acc2[1][0]);
            acc2[1][1] = ffma2(wv.y, hA.y, acc2[1][1]);
            acc2[1][2] = ffma2(wv.y, hB.x, acc2[1][2]);
            acc2[1][3] = ffma2(wv.y, hB.y, acc2[1][3]);
        }
#pragma unroll
        for (int p = 0; p < 2; p++) {
            float2 p0 = unpk(acc2[p][0]), p1 = unpk(acc2[p][1]);
            float2 p2 = unpk(acc2[p][2]), p3 = unpk(acc2[p][3]);
            int rr0 = r0 + 2 * p, rr1 = rr0 + 1;
            *(float4*)&RED[(w * 64 + rr0) * GB + b0] = make_float4(p0.x, p1.x, p2.x, p3.x);
            *(float4*)&RED[(w * 64 + rr1) * GB + b0] = make_float4(p0.y, p1.y, p2.y, p3.y);
        }
        __syncthreads();                                   // (2)

        // 3) reduce + activations + state update + h store (tid<128)
        if (tid < 128) {
            float gv[4];
#pragma unroll
            for (int gate = 0; gate < 4; gate++) {
                int r = gate * 16 + sjl;
                float s = GT[r * GB + sbb];
#pragma unroll
                for (int ws = 0; ws < 8; ws++) s += RED[(ws * 64 + r) * GB + sbb];
                gv[gate] = s;
            }
            float gg = ftanh(gv[0]);
            float ii = fsig(gv[1]);
            float ff = fsig(gv[2]);
            float oo = fsig(gv[3]);
            creg = ff * creg + ii * gg;
            float h = oo * ftanh(creg);
            ghg[((size_t)t * HH + j0 + sjl) * GB + sbb] = h;
        }
        __syncthreads();                                   // (3)

        // 4) publish (release), rotate xp prefetch (depth 2), central poll,
        //    BAR fan-out
        if (tid == 0) st_rel(&flags[blockIdx.x * 32], ebase + (unsigned)(t + 1));
        if (tid < 128) {
            xpv0 = xpv1;
            if (t + 2 < TT)
                xpv1 = __ldcg((const float4*)(xpsrc + (size_t)(t + 2) * G4 * BB));
        }
        if (tid < GSZ) {
            unsigned want = ebase + (unsigned)(t + 1);
            while (ld_acq(&flags[(group * GSZ + tid) * 32]) < want) { }
        }
        __syncthreads();                                   // (4)
    }
}

// ---------------------------------------------------------------------------
// Final FC: out[b][o] = sum_k h_{T-1}[k][b] * fcW[o][k] + fcb[o]
// ---------------------------------------------------------------------------
__global__ void fc_kernel(const float* __restrict__ fcW,
                          const float* __restrict__ fcb,
                          float* __restrict__ out)
{
    const int b = blockIdx.x;
    const int o = threadIdx.x;
    const int g = b >> 3, bb = b & 7;
    __shared__ float hsh[HH];
    for (int k = threadIdx.x; k < HH; k += blockDim.x)
        hsh[k] = g_h[(((size_t)g * TT + TT - 1) * HH + k) * GB + bb];
    __syncthreads();
    float acc = 0.f;
    const float* wv = fcW + (size_t)o * HH;
#pragma unroll 8
    for (int k = 0; k < HH; k += 4) {
        float4 w4 = *(const float4*)(wv + k);
        acc += w4.x * hsh[k] + w4.y * hsh[k + 1] + w4.z * hsh[k + 2] + w4.w * hsh[k + 3];
    }
    out[(size_t)b * OO + o] = acc + fcb[o];
}

// ---------------------------------------------------------------------------
extern "C" void kernel_launch(void* const* d_in, const int* in_sizes, int n_in,
                              void* d_out, int out_size)
{
    const float* x   = (const float*)d_in[0];
    const float* Wx0 = (const float*)d_in[1];
    const float* bx0 = (const float*)d_in[2];
    const float* Wh0 = (const float*)d_in[3];
    const float* bh0 = (const float*)d_in[4];
    const float* Wx1 = (const float*)d_in[5];
    const float* bx1 = (const float*)d_in[6];
    const float* Wh1 = (const float*)d_in[7];
    const float* bh1 = (const float*)d_in[8];
    const float* fcW = (const float*)d_in[9];
    const float* fcb = (const float*)d_in[10];
    float* out = (float*)d_out;
    (void)in_sizes; (void)n_in; (void)out_size;

    float* xp = nullptr; cudaGetSymbolAddress((void**)&xp, g_xp);
    float* gh = nullptr; cudaGetSymbolAddress((void**)&gh, g_h);
    float* wt = nullptr; cudaGetSymbolAddress((void**)&wt, g_wt);

    cudaFuncSetAttribute(lstm_kernel,
                         cudaFuncAttributeMaxDynamicSharedMemorySize,
                         LSTM_SMEM_BYTES);

    dim3 gproj(G4 / 256, MM / 64);

    // ---- Layer 0 ----  (lstm0 at launch index 3 for ncu capture)
    transpose_w_kernel<<<dim3(G4 / 32, DD / 32), 256>>>(Wx0, wt, DD);      // 0
    transpose_x_kernel<<<dim3(TT, DD / 32), 256>>>(x, gh);                 // 1 (+flag reset)
    proj_kernel<<<gproj, 256>>>(wt, bx0, bh0, gh, DD, xp);                 // 2
    lstm_kernel<<<NCTA, 256, LSTM_SMEM_BYTES>>>(Wh0, xp, gh, 0u);          // 3

    // ---- Layer 1 ----
    transpose_w_kernel<<<dim3(G4 / 32, HH / 32), 256>>>(Wx1, wt, HH);      // 4
    proj_kernel<<<gproj, 256>>>(wt, bx1, bh1, gh, HH, xp);                 // 5
    lstm_kernel<<<NCTA, 256, LSTM_SMEM_BYTES>>>(Wh1, xp, gh, (unsigned)TT);// 6

    fc_kernel<<<BB, 256>>>(fcW, fcb, out);                                 // 7
}

// round 12
// speedup vs baseline: 1.2952x; 1.2952x over previous
#include <cuda_runtime.h>
#include <math.h>

#define TT 1024
#define BB 32
#define DD 256
#define HH 512
#define G4 2048   // 4*H
#define OO 256
#define MM (TT * BB)
#define NCTA 128
#define NGRP 4
#define GSZ  32     // CTAs per group
#define GB   8      // batch per group

typedef unsigned long long u64;

// ---- packed fp32x2 helpers (sm_103a FFMA2, exact fp32 numerics) ----
__device__ __forceinline__ u64 ffma2(u64 a, u64 b, u64 c) {
    u64 d; asm("fma.rn.f32x2 %0, %1, %2, %3;" : "=l"(d) : "l"(a), "l"(b), "l"(c)); return d;
}
__device__ __forceinline__ u64 dup2(float x) {
    u64 d; unsigned xi = __float_as_uint(x);
    asm("mov.b64 %0, {%1, %1};" : "=l"(d) : "r"(xi)); return d;
}
__device__ __forceinline__ float2 unpk(u64 a) {
    unsigned lo, hi; asm("mov.b64 {%0, %1}, %2;" : "=r"(lo), "=r"(hi) : "l"(a));
    return make_float2(__uint_as_float(lo), __uint_as_float(hi));
}
__device__ __forceinline__ float fsig(float y) { return __fdividef(1.f, 1.f + __expf(-y)); }
__device__ __forceinline__ float ftanh(float x) { return 2.f * fsig(2.f * x) - 1.f; }

// ---- gpu-scope acquire/release flag ops ----
__device__ __forceinline__ unsigned ld_acq(const unsigned int* p) {
    unsigned v; asm volatile("ld.acquire.gpu.global.u32 %0, [%1];" : "=r"(v) : "l"(p) : "memory");
    return v;
}
__device__ __forceinline__ void st_rel(unsigned int* p, unsigned v) {
    asm volatile("st.release.gpu.global.u32 [%0], %1;" :: "l"(p), "r"(v) : "memory");
}

// Scratch (device globals: allocation-free rule)
__device__ float g_xp[(size_t)TT * G4 * BB];          // [T][4H][B] pre-activations (+ biases)
__device__ float g_h[(size_t)NGRP * TT * HH * GB];    // [g][t][k][8] group-local k-major data
__device__ float g_wt[(size_t)HH * G4];               // [K][4H] k-major weights (per layer)
__device__ unsigned int g_flag[NCTA * 32];            // per-CTA epoch flags, 128B apart

// ---------------------------------------------------------------------------
// Transpose x[B][T][D] -> g_h[(g*T + t)*D + d][8] ; block(0,0) zeroes flags.
// ---------------------------------------------------------------------------
__global__ void transpose_x_kernel(const float* __restrict__ x, float* __restrict__ gh)
{
    const int t  = blockIdx.x;
    const int d0 = blockIdx.y * 32;
    const int tid = threadIdx.x;
    if (blockIdx.x == 0 && blockIdx.y == 0 && tid < NCTA) g_flag[tid * 32] = 0u;
    __shared__ float s[32][36];
    {
        int b  = tid >> 3;
        int d4 = (tid & 7) * 4;
        float4 v = *(const float4*)(x + (size_t)b * TT * DD + (size_t)t * DD + d0 + d4);
        s[b][d4 + 0] = v.x; s[b][d4 + 1] = v.y; s[b][d4 + 2] = v.z; s[b][d4 + 3] = v.w;
    }
    __syncthreads();
    {
        int d  = tid >> 3;
        int b4 = (tid & 7) * 4;
        int g  = b4 >> 3;
        int off= b4 & 7;
        float4 o = make_float4(s[b4 + 0][d], s[b4 + 1][d], s[b4 + 2][d], s[b4 + 3][d]);
        *(float4*)(gh + (((size_t)g * TT + t) * DD + d0 + d) * GB + off) = o;
    }
}

// ---------------------------------------------------------------------------
// Transpose W[2048][K] -> wt[K][2048].
// ---------------------------------------------------------------------------
__global__ void transpose_w_kernel(const float* __restrict__ W, float* __restrict__ wt, int K)
{
    const int n0 = blockIdx.x * 32;
    const int k0 = blockIdx.y * 32;
    const int tid = threadIdx.x;
    __shared__ float s[32][36];
    {
        int n  = tid >> 3;
        int k4 = (tid & 7) * 4;
        float4 v = *(const float4*)(W + (size_t)(n0 + n) * K + k0 + k4);
        s[n][k4 + 0] = v.x; s[n][k4 + 1] = v.y; s[n][k4 + 2] = v.z; s[n][k4 + 3] = v.w;
    }
    __syncthreads();
    {
        int k  = tid >> 3;
        int n4 = (tid & 7) * 4;
        float4 o = make_float4(s[n4 + 0][k], s[n4 + 1][k], s[n4 + 2][k], s[n4 + 3][k]);
        *(float4*)(wt + (size_t)(k0 + k) * G4 + n0 + n4) = o;
    }
}

// ---------------------------------------------------------------------------
// Projection GEMM: xp[t][n][b] = sum_k wt[k][n] * gh[(g*T+t)*K + k][b&7] + bias
// ---------------------------------------------------------------------------
__global__ void __launch_bounds__(256, 2)
proj_kernel(const float* __restrict__ wt,
            const float* __restrict__ bx,
            const float* __restrict__ bh,
            const float* __restrict__ gh,
            int K,
            float* __restrict__ xp)
{
    const int n0  = blockIdx.x * 256;
    const int m0  = blockIdx.y * 64;
    const int tid = threadIdx.x;
    const int ng  = tid >> 3;
    const int mg  = tid & 7;

    __shared__ float Ws[16][264];
    __shared__ float Xs[16][72];

    u64 acc[4][8];
#pragma unroll
    for (int i = 0; i < 4; i++)
#pragma unroll
        for (int j = 0; j < 8; j++) acc[i][j] = 0ULL;

    const int xk  = tid >> 4;
    const int xm4 = (tid & 15) * 4;
    const int xt  = (m0 >> 5) + (xm4 >> 5);
    const int xb4 = xm4 & 31;
    const int xg  = xb4 >> 3;
    const int xoff= xb4 & 7;
    const float* xsrc = gh + (((size_t)xg * TT + xt) * K) * GB + xoff;

    for (int k0 = 0; k0 < K; k0 += 16) {
        __syncthreads();
#pragma unroll
        for (int i = 0; i < 4; i++) {
            int id = i * 256 + tid;
            int k  = id >> 6;
            int n4 = (id & 63) * 4;
            float4 v = *(const float4*)(wt + (size_t)(k0 + k) * G4 + n0 + n4);
            *(float4*)&Ws[k][n4] = v;
        }
        {
            float4 v = *(const float4*)(xsrc + (size_t)(k0 + xk) * GB);
            *(float4*)&Xs[xk][xm4] = v;
        }
        __syncthreads();

#pragma unroll
        for (int k = 0; k < 16; k++) {
            const ulonglong2* wp = (const ulonglong2*)&Ws[k][ng * 8];
            ulonglong2 wA = wp[0];
            ulonglong2 wB = wp[1];
            float4 x0 = *(const float4*)&Xs[k][mg * 8];
            float4 x1 = *(const float4*)&Xs[k][mg * 8 + 4];
            u64 xd[8] = {dup2(x0.x), dup2(x0.y), dup2(x0.z), dup2(x0.w),
                         dup2(x1.x), dup2(x1.y), dup2(x1.z), dup2(x1.w)};
            u64 wv[4] = {wA.x, wA.y, wB.x, wB.y};
#pragma unroll
            for (int i = 0; i < 4; i++)
#pragma unroll
                for (int j = 0; j < 8; j++)
                    acc[i][j] = ffma2(wv[i], xd[j], acc[i][j]);
        }
    }

    float bias[8];
#pragma unroll
    for (int r = 0; r < 8; r++) {
        int n = n0 + ng * 8 + r;
        bias[r] = bx[n] + bh[n];
    }
    const int ot = (m0 >> 5) + (mg >> 2);
    const int ob = (mg & 3) * 8;
    float* outb = xp + ((size_t)ot * G4 + n0 + ng * 8) * BB + ob;
#pragma unroll
    for (int i = 0; i < 4; i++) {
        float2 p[8];
#pragma unroll
        for (int j = 0; j < 8; j++) p[j] = unpk(acc[i][j]);
        int rlo = 2 * i, rhi = 2 * i + 1;
        *(float4*)(outb + (size_t)rlo * BB)     = make_float4(p[0].x + bias[rlo], p[1].x + bias[rlo], p[2].x + bias[rlo], p[3].x + bias[rlo]);
        *(float4*)(outb + (size_t)rlo * BB + 4) = make_float4(p[4].x + bias[rlo], p[5].x + bias[rlo], p[6].x + bias[rlo], p[7].x + bias[rlo]);
        *(float4*)(outb + (size_t)rhi * BB)     = make_float4(p[0].y + bias[rhi], p[1].y + bias[rhi], p[2].y + bias[rhi], p[3].y + bias[rhi]);
        *(float4*)(outb + (size_t)rhi * BB + 4) = make_float4(p[4].y + bias[rhi], p[5].y + bias[rhi], p[6].y + bias[rhi], p[7].y + bias[rhi]);
    }
}

// ---------------------------------------------------------------------------
// Persistent LSTM — R6 phases, warp-role overlapped tail:
//   warps 0-3: reduce/act/h-store -> named bar 1 -> tid0 release-publish
//   warps 4-7: warp7 polls t+1 -> named bar 2 -> load full 16KB h(t) to HSH
//   one __syncthreads joins. 2 block syncs/step instead of 4.
// ---------------------------------------------------------------------------
#define LSTM_SMEM_FLOATS (512*64 + 512*8 + 8*64*8 + 64*8)
#define LSTM_SMEM_BYTES  (LSTM_SMEM_FLOATS * 4)

__global__ void __launch_bounds__(256, 1)
lstm_kernel(const float* __restrict__ Wh,   // [4][H][H]
            const float* __restrict__ xp,   // [T][4H][B]
            float* __restrict__ gh,         // [g][T][512][8]
            unsigned int ebase)             // flag epoch base (layer*TT)
{
    extern __shared__ float sm[];
    float* WSH = sm;                    // [k][64 rows]
    float* HSH = WSH + 512 * 64;        // [k][8]
    float* RED = HSH + 512 * 8;         // [w][64 rows][8]
    float* GT  = RED + 8 * 64 * 8;      // [64 rows][8]

    const int tid   = threadIdx.x;
    const int rank  = blockIdx.x & 31;
    const int group = blockIdx.x >> 5;
    const int j0    = rank * 16;
    const int gb0   = group * GB;
    const int w     = tid >> 5;
    const int lane  = tid & 31;
    const int rgr   = lane >> 1;
    const int bgr   = lane & 1;

    unsigned int* flags = g_flag;

    // Preload Wh slice transposed: rows r = gate*16 + jl
    for (int f = tid; f < 64 * 128; f += 256) {
        int r  = f >> 7;
        int c4 = (f & 127) * 4;
        int gate = r >> 4, jl = r & 15;
        float4 v = *(const float4*)(Wh + ((size_t)gate * HH + j0 + jl) * HH + c4);
        WSH[(c4 + 0) * 64 + r] = v.x; WSH[(c4 + 1) * 64 + r] = v.y;
        WSH[(c4 + 2) * 64 + r] = v.z; WSH[(c4 + 3) * 64 + r] = v.w;
    }
    for (int i = tid; i < 512 * 8; i += 256) HSH[i] = 0.f;   // h_{-1} = 0
    __syncthreads();

    // Per-thread fixed indices
    const int gr   = tid >> 1;          // GT staging row (tid<128)
    const int ghalf= tid & 1;
    const int ggate= gr >> 4, gjl = gr & 15;
    const float* xpsrc = xp + ((size_t)ggate * HH + j0 + gjl) * BB + gb0 + ghalf * 4;
    const int sjl  = tid >> 3;          // state j (tid<128)
    const int sbb  = tid & 7;

    float* ghg = gh + (size_t)group * TT * HH * GB;
    float creg = 0.f;                   // cell state in register (tid<128)

    // Prologue prefetch of xp[0]
    float4 xpv;
    if (tid < 128) xpv = __ldcg((const float4*)xpsrc);

    for (int t = 0; t < TT; t++) {
        // 1) stage GT (tid<128; readers synced via syncB below), then GEMM.
        //    HSH holds h_{t-1}, written before last iteration's syncA.
        if (tid < 128) *(float4*)&GT[gr * GB + ghalf * 4] = xpv;

        u64 acc2[2][4];
#pragma unroll
        for (int p = 0; p < 2; p++)
#pragma unroll
            for (int j = 0; j < 4; j++) acc2[p][j] = 0ULL;

        const int kbase = w * 64;
        const int r0 = rgr * 4;
        const int b0 = bgr * 4;
#pragma unroll 8
        for (int kk = 0; kk < 64; kk++) {
            int k = kbase + kk;
            ulonglong2 wv = *(const ulonglong2*)&WSH[k * 64 + r0];
            float4 h4 = *(const float4*)&HSH[k * GB + b0];
            u64 hd[4] = {dup2(h4.x), dup2(h4.y), dup2(h4.z), dup2(h4.w)};
#pragma unroll
            for (int j = 0; j < 4; j++) {
                acc2[0][j] = ffma2(wv.x, hd[j], acc2[0][j]);
                acc2[1][j] = ffma2(wv.y, hd[j], acc2[1][j]);
            }
        }
#pragma unroll
        for (int p = 0; p < 2; p++) {
            float2 p0 = unpk(acc2[p][0]), p1 = unpk(acc2[p][1]);
            float2 p2 = unpk(acc2[p][2]), p3 = unpk(acc2[p][3]);
            int rr0 = r0 + 2 * p, rr1 = rr0 + 1;
            *(float4*)&RED[(w * 64 + rr0) * GB + b0] = make_float4(p0.x, p1.x, p2.x, p3.x);
            *(float4*)&RED[(w * 64 + rr1) * GB + b0] = make_float4(p0.y, p1.y, p2.y, p3.y);
        }
        __syncthreads();                                   // syncB

        if (w < 4) {
            // 2a) reduce + activations + state update + h store (warps 0-3)
            float gv[4];
#pragma unroll
            for (int gate = 0; gate < 4; gate++) {
                int r = gate * 16 + sjl;
                float s = GT[r * GB + sbb];
#pragma unroll
                for (int ws = 0; ws < 8; ws++) s += RED[(ws * 64 + r) * GB + sbb];
                gv[gate] = s;
            }
            float gg = ftanh(gv[0]);
            float ii = fsig(gv[1]);
            float ff = fsig(gv[2]);
            float oo = fsig(gv[3]);
            creg = ff * creg + ii * gg;
            float h = oo * ftanh(creg);
            ghg[((size_t)t * HH + j0 + sjl) * GB + sbb] = h;
            if (t + 1 < TT)
                xpv = __ldcg((const float4*)(xpsrc + (size_t)(t + 1) * G4 * BB));
            asm volatile("bar.sync 1, 128;" ::: "memory");  // h stores done (warps 0-3)
            if (tid == 0) st_rel(&flags[blockIdx.x * 32], ebase + (unsigned)(t + 1));
        } else {
            // 2b) poll (warp 7) overlapped with warps 0-3's state phase,
            //     then warps 4-7 load the full 16KB h(t) into HSH for t+1
            if (w == 7) {
                unsigned want = ebase + (unsigned)(t + 1);
                while (ld_acq(&flags[(group * GSZ + lane) * 32]) < want) { }
            }
            asm volatile("bar.sync 2, 128;" ::: "memory");  // poll done (warps 4-7)
            if (t + 1 < TT) {
                const float* hb = ghg + (size_t)t * HH * GB;
                const int tid2 = tid - 128;
                float4 hv[8];
#pragma unroll
                for (int i = 0; i < 8; i++)
                    hv[i] = __ldcg((const float4*)(hb + (size_t)(i * 128 + tid2) * 4));
#pragma unroll
                for (int i = 0; i < 8; i++)
                    *(float4*)&HSH[(i * 128 + tid2) * 4] = hv[i];
            }
        }
        __syncthreads();                                   // syncA
    }
}

// ---------------------------------------------------------------------------
// Final FC: out[b][o] = sum_k h_{T-1}[k][b] * fcW[o][k] + fcb[o]
// ---------------------------------------------------------------------------
__global__ void fc_kernel(const float* __restrict__ fcW,
                          const float* __restrict__ fcb,
                          float* __restrict__ out)
{
    const int b = blockIdx.x;
    const int o = threadIdx.x;
    const int g = b >> 3, bb = b & 7;
    __shared__ float hsh[HH];
    for (int k = threadIdx.x; k < HH; k += blockDim.x)
        hsh[k] = g_h[(((size_t)g * TT + TT - 1) * HH + k) * GB + bb];
    __syncthreads();
    float acc = 0.f;
    const float* wv = fcW + (size_t)o * HH;
#pragma unroll 8
    for (int k = 0; k < HH; k += 4) {
        float4 w4 = *(const float4*)(wv + k);
        acc += w4.x * hsh[k] + w4.y * hsh[k + 1] + w4.z * hsh[k + 2] + w4.w * hsh[k + 3];
    }
    out[(size_t)b * OO + o] = acc + fcb[o];
}

// ---------------------------------------------------------------------------
extern "C" void kernel_launch(void* const* d_in, const int* in_sizes, int n_in,
                              void* d_out, int out_size)
{
    const float* x   = (const float*)d_in[0];
    const float* Wx0 = (const float*)d_in[1];
    const float* bx0 = (const float*)d_in[2];
    const float* Wh0 = (const float*)d_in[3];
    const float* bh0 = (const float*)d_in[4];
    const float* Wx1 = (const float*)d_in[5];
    const float* bx1 = (const float*)d_in[6];
    const float* Wh1 = (const float*)d_in[7];
    const float* bh1 = (const float*)d_in[8];
    const float* fcW = (const float*)d_in[9];
    const float* fcb = (const float*)d_in[10];
    float* out = (float*)d_out;
    (void)in_sizes; (void)n_in; (void)out_size;

    float* xp = nullptr; cudaGetSymbolAddress((void**)&xp, g_xp);
    float* gh = nullptr; cudaGetSymbolAddress((void**)&gh, g_h);
    float* wt = nullptr; cudaGetSymbolAddress((void**)&wt, g_wt);

    cudaFuncSetAttribute(lstm_kernel,
                         cudaFuncAttributeMaxDynamicSharedMemorySize,
                         LSTM_SMEM_BYTES);

    dim3 gproj(G4 / 256, MM / 64);

    // ---- Layer 0 ----  (lstm0 at launch index 3 for ncu capture)
    transpose_w_kernel<<<dim3(G4 / 32, DD / 32), 256>>>(Wx0, wt, DD);      // 0
    transpose_x_kernel<<<dim3(TT, DD / 32), 256>>>(x, gh);                 // 1 (+flag reset)
    proj_kernel<<<gproj, 256>>>(wt, bx0, bh0, gh, DD, xp);                 // 2
    lstm_kernel<<<NCTA, 256, LSTM_SMEM_BYTES>>>(Wh0, xp, gh, 0u);          // 3

    // ---- Layer 1 ----
    transpose_w_kernel<<<dim3(G4 / 32, HH / 32), 256>>>(Wx1, wt, HH);      // 4
    proj_kernel<<<gproj, 256>>>(wt, bx1, bh1, gh, HH, xp);                 // 5
    lstm_kernel<<<NCTA, 256, LSTM_SMEM_BYTES>>>(Wh1, xp, gh, (unsigned)TT);// 6

    fc_kernel<<<BB, 256>>>(fcW, fcb, out);                                 // 7
}